// round 1
// baseline (speedup 1.0000x reference)
#include <cuda_runtime.h>

#define HID 5
#define G4 20      // 4*HID gates
#define HDIM 2048
#define BSZ 16384

// scratch for per-row lengths (device global: no allocations allowed)
__device__ int g_lengths[BSZ];

// ---------------------------------------------------------------------------
// Kernel 1: per-row nonzero count (== ragged length, matching reference mask)
// One block per row, coalesced float4 reads.
// ---------------------------------------------------------------------------
__global__ void len_kernel(const float* __restrict__ x) {
    int b = blockIdx.x;
    const float4* row = reinterpret_cast<const float4*>(x + (size_t)b * HDIM);
    int tid = threadIdx.x;
    int cnt = 0;
#pragma unroll
    for (int i = 0; i < 2; i++) {
        float4 v = row[tid + i * 256];
        cnt += (v.x != 0.f) + (v.y != 0.f) + (v.z != 0.f) + (v.w != 0.f);
    }
    __shared__ int s[8];
#pragma unroll
    for (int o = 16; o > 0; o >>= 1) cnt += __shfl_down_sync(0xffffffffu, cnt, o);
    if ((tid & 31) == 0) s[tid >> 5] = cnt;
    __syncthreads();
    if (tid < 8) {
        int v = s[tid];
#pragma unroll
        for (int o = 4; o > 0; o >>= 1) v += __shfl_down_sync(0xffu, v, o);
        if (tid == 0) g_lengths[b] = v;
    }
}

// ---------------------------------------------------------------------------
// Fast nonlinearities: HW MUFU tanh
// ---------------------------------------------------------------------------
__device__ __forceinline__ float fast_tanh(float v) {
    float r;
    asm("tanh.approx.f32 %0, %1;" : "=f"(r) : "f"(v));
    return r;
}
__device__ __forceinline__ float fast_sig(float v) {
    // sigmoid(x) = 0.5*tanh(0.5x) + 0.5
    return fmaf(fast_tanh(0.5f * v), 0.5f, 0.5f);
}

// ---------------------------------------------------------------------------
// Kernel 2: one thread per sequence, full LSTM recurrence in registers.
// Weights (140 floats) register-resident; x streamed 32B/thread per 8 steps
// with software prefetch.
// ---------------------------------------------------------------------------
__global__ void __launch_bounds__(64, 1) lstm_kernel(
    const float* __restrict__ x,
    const float* __restrict__ W_ih,
    const float* __restrict__ W_hh,
    const float* __restrict__ b_ih,
    const float* __restrict__ b_hh,
    float* __restrict__ out)
{
    int b = blockIdx.x * blockDim.x + threadIdx.x;

    float wih[G4], bs[G4], whh[G4][HID];
#pragma unroll
    for (int g = 0; g < G4; g++) {
        wih[g] = W_ih[g];
        bs[g]  = b_ih[g] + b_hh[g];
#pragma unroll
        for (int j = 0; j < HID; j++) whh[g][j] = W_hh[g * HID + j];
    }

    const int len = g_lengths[b];
    const float* row = x + (size_t)b * HDIM;

    float h[HID] = {0.f, 0.f, 0.f, 0.f, 0.f};
    float c[HID] = {0.f, 0.f, 0.f, 0.f, 0.f};

    float4 a0 = make_float4(0.f, 0.f, 0.f, 0.f);
    float4 a1 = a0;
    if (len > 0) {
        a0 = *reinterpret_cast<const float4*>(row);
        a1 = *reinterpret_cast<const float4*>(row + 4);
    }

    for (int t0 = 0; t0 < len; t0 += 8) {
        // prefetch next 8 timesteps (always in-bounds: HDIM multiple of 8)
        float4 n0 = a0, n1 = a1;
        const int nt = t0 + 8;
        if (nt < HDIM) {
            n0 = *reinterpret_cast<const float4*>(row + nt);
            n1 = *reinterpret_cast<const float4*>(row + nt + 4);
        }

        float xs[8] = {a0.x, a0.y, a0.z, a0.w, a1.x, a1.y, a1.z, a1.w};
        const int nrem = len - t0;

#pragma unroll
        for (int k = 0; k < 8; k++) {
            if (k < nrem) {
                const float xv = xs[k];
                float gates[G4];
#pragma unroll
                for (int g = 0; g < G4; g++) {
                    float acc = fmaf(xv, wih[g], bs[g]);
#pragma unroll
                    for (int j = 0; j < HID; j++)
                        acc = fmaf(h[j], whh[g][j], acc);
                    gates[g] = acc;
                }
#pragma unroll
                for (int u = 0; u < HID; u++) {
                    const float ig = fast_sig(gates[u]);
                    const float fg = fast_sig(gates[HID + u]);
                    const float gg = fast_tanh(gates[2 * HID + u]);
                    const float og = fast_sig(gates[3 * HID + u]);
                    const float cn = fmaf(fg, c[u], ig * gg);
                    c[u] = cn;
                    h[u] = og * fast_tanh(cn);
                }
            }
        }
        a0 = n0;
        a1 = n1;
    }

#pragma unroll
    for (int u = 0; u < HID; u++) out[b * HID + u] = h[u];
}

// ---------------------------------------------------------------------------
extern "C" void kernel_launch(void* const* d_in, const int* in_sizes, int n_in,
                              void* d_out, int out_size) {
    const float* x    = (const float*)d_in[0];
    const float* W_ih = (const float*)d_in[1];
    const float* W_hh = (const float*)d_in[2];
    const float* b_ih = (const float*)d_in[3];
    const float* b_hh = (const float*)d_in[4];
    float* out = (float*)d_out;

    len_kernel<<<BSZ, 256>>>(x);
    lstm_kernel<<<BSZ / 64, 64>>>(x, W_ih, W_hh, b_ih, b_hh, out);
}

// round 2
// speedup vs baseline: 1.1747x; 1.1747x over previous
#include <cuda_runtime.h>

#define HID 5
#define G4 20      // 4*HID gates
#define NPAIR 10   // packed gate pairs
#define HDIM 2048
#define BSZ 16384

typedef unsigned long long u64;

// scratch for per-row lengths (device global: no allocations allowed)
__device__ int g_lengths[BSZ];

// ---------------------------------------------------------------------------
// Kernel 1: per-row nonzero count (== ragged length, matching reference mask)
// ---------------------------------------------------------------------------
__global__ void len_kernel(const float* __restrict__ x) {
    int b = blockIdx.x;
    const float4* row = reinterpret_cast<const float4*>(x + (size_t)b * HDIM);
    int tid = threadIdx.x;
    int cnt = 0;
#pragma unroll
    for (int i = 0; i < 2; i++) {
        float4 v = row[tid + i * 256];
        cnt += (v.x != 0.f) + (v.y != 0.f) + (v.z != 0.f) + (v.w != 0.f);
    }
    __shared__ int s[8];
#pragma unroll
    for (int o = 16; o > 0; o >>= 1) cnt += __shfl_down_sync(0xffffffffu, cnt, o);
    if ((tid & 31) == 0) s[tid >> 5] = cnt;
    __syncthreads();
    if (tid < 8) {
        int v = s[tid];
#pragma unroll
        for (int o = 4; o > 0; o >>= 1) v += __shfl_down_sync(0xffu, v, o);
        if (tid == 0) g_lengths[b] = v;
    }
}

// ---------------------------------------------------------------------------
// f32x2 packed-math helpers (Blackwell FFMA2 path — only reachable via PTX)
// ---------------------------------------------------------------------------
__device__ __forceinline__ u64 pk2(float lo, float hi) {
    u64 r; asm("mov.b64 %0, {%1,%2};" : "=l"(r) : "f"(lo), "f"(hi)); return r;
}
__device__ __forceinline__ void up2(u64 v, float& lo, float& hi) {
    asm("mov.b64 {%0,%1}, %2;" : "=f"(lo), "=f"(hi) : "l"(v));
}
__device__ __forceinline__ u64 fma2_(u64 a, u64 b, u64 c) {
    u64 d; asm("fma.rn.f32x2 %0, %1, %2, %3;" : "=l"(d) : "l"(a), "l"(b), "l"(c)); return d;
}
__device__ __forceinline__ u64 mul2_(u64 a, u64 b) {
    u64 d; asm("mul.rn.f32x2 %0, %1, %2;" : "=l"(d) : "l"(a), "l"(b)); return d;
}

__device__ __forceinline__ float fast_tanh(float v) {
    float r; asm("tanh.approx.f32 %0, %1;" : "=f"(r) : "f"(v)); return r;
}

// gate slot permutation: slots [i(0-4), f(5-9), o(10-14), g(15-19)]
// original W rows:             [i(0-4), f(5-9), g(10-14), o(15-19)]
__device__ __forceinline__ int gperm(int s) {
    return (s < 10) ? s : (s < 15 ? s + 5 : s - 5);
}

// packed constant {0.5f, 0.5f}
#define HALF2 0x3F0000003F000000ULL

// ---------------------------------------------------------------------------
// Kernel 2: one thread per sequence; gates packed into f32x2 pairs.
// ---------------------------------------------------------------------------
__global__ void __launch_bounds__(64, 1) lstm_kernel(
    const float* __restrict__ x,
    const float* __restrict__ W_ih,
    const float* __restrict__ W_hh,
    const float* __restrict__ b_ih,
    const float* __restrict__ b_hh,
    float* __restrict__ out)
{
    int b = blockIdx.x * blockDim.x + threadIdx.x;

    // packed weights: pair p covers gate slots (2p, 2p+1)
    u64 wih2[NPAIR], bs2[NPAIR], whh2[NPAIR][HID];
#pragma unroll
    for (int p = 0; p < NPAIR; p++) {
        int glo = gperm(2 * p), ghi = gperm(2 * p + 1);
        wih2[p] = pk2(W_ih[glo], W_ih[ghi]);
        bs2[p]  = pk2(b_ih[glo] + b_hh[glo], b_ih[ghi] + b_hh[ghi]);
#pragma unroll
        for (int j = 0; j < HID; j++)
            whh2[p][j] = pk2(W_hh[glo * HID + j], W_hh[ghi * HID + j]);
    }

    const int len = g_lengths[b];
    const float* row = x + (size_t)b * HDIM;

    float h[HID] = {0.f, 0.f, 0.f, 0.f, 0.f};
    float c[HID] = {0.f, 0.f, 0.f, 0.f, 0.f};

    float4 a0 = make_float4(0.f, 0.f, 0.f, 0.f);
    float4 a1 = a0;
    if (len > 0) {
        a0 = *reinterpret_cast<const float4*>(row);
        a1 = *reinterpret_cast<const float4*>(row + 4);
    }

    for (int t0 = 0; t0 < len; t0 += 8) {
        // prefetch next 8 timesteps (HDIM is a multiple of 8)
        float4 n0 = a0, n1 = a1;
        const int nt = t0 + 8;
        if (nt < HDIM) {
            n0 = *reinterpret_cast<const float4*>(row + nt);
            n1 = *reinterpret_cast<const float4*>(row + nt + 4);
        }

        float xs[8] = {a0.x, a0.y, a0.z, a0.w, a1.x, a1.y, a1.z, a1.w};
        const int nrem = len - t0;

#pragma unroll
        for (int k = 0; k < 8; k++) {
            if (k < nrem) {
                const u64 x2 = pk2(xs[k], xs[k]);
                u64 h2[HID];
#pragma unroll
                for (int j = 0; j < HID; j++) h2[j] = pk2(h[j], h[j]);

                u64 acc[NPAIR];
#pragma unroll
                for (int p = 0; p < NPAIR; p++) {
                    u64 a = fma2_(x2, wih2[p], bs2[p]);
#pragma unroll
                    for (int j = 0; j < HID; j++)
                        a = fma2_(h2[j], whh2[p][j], a);
                    acc[p] = a;
                }

                // pre-scale sigmoid inputs by 0.5: slots 0..13 packed (pairs 0..6)
#pragma unroll
                for (int p = 0; p < 7; p++) acc[p] = mul2_(acc[p], HALF2);

                float gs[G4];
#pragma unroll
                for (int p = 0; p < NPAIR; p++) up2(acc[p], gs[2 * p], gs[2 * p + 1]);
                gs[14] *= 0.5f;  // slot 14 sits in unscaled pair 7

                // tanh everything; sigmoid slots finish with fma(t,0.5,0.5)
                float sg[15], tg[HID];
#pragma unroll
                for (int s = 0; s < 15; s++) sg[s] = fmaf(fast_tanh(gs[s]), 0.5f, 0.5f);
#pragma unroll
                for (int u = 0; u < HID; u++) tg[u] = fast_tanh(gs[15 + u]);

#pragma unroll
                for (int u = 0; u < HID; u++) {
                    const float ig = sg[u];
                    const float fg = sg[5 + u];
                    const float og = sg[10 + u];
                    const float gg = tg[u];
                    const float cn = fmaf(fg, c[u], ig * gg);
                    c[u] = cn;
                    h[u] = og * fast_tanh(cn);
                }
            }
        }
        a0 = n0;
        a1 = n1;
    }

#pragma unroll
    for (int u = 0; u < HID; u++) out[b * HID + u] = h[u];
}

// ---------------------------------------------------------------------------
extern "C" void kernel_launch(void* const* d_in, const int* in_sizes, int n_in,
                              void* d_out, int out_size) {
    const float* x    = (const float*)d_in[0];
    const float* W_ih = (const float*)d_in[1];
    const float* W_hh = (const float*)d_in[2];
    const float* b_ih = (const float*)d_in[3];
    const float* b_hh = (const float*)d_in[4];
    float* out = (float*)d_out;

    len_kernel<<<BSZ, 256>>>(x);
    lstm_kernel<<<BSZ / 64, 64>>>(x, W_ih, W_hh, b_ih, b_hh, out);
}

// round 3
// speedup vs baseline: 1.2090x; 1.0292x over previous
#include <cuda_runtime.h>

#define HID 5
#define HDIM 2048
#define BSZ 16384

typedef unsigned long long u64;

__device__ int g_lengths[BSZ];

// ---------------------------------------------------------------------------
// Kernel 1: per-row nonzero count (ragged length, matches reference mask)
// ---------------------------------------------------------------------------
__global__ void len_kernel(const float* __restrict__ x) {
    int b = blockIdx.x;
    const float4* row = reinterpret_cast<const float4*>(x + (size_t)b * HDIM);
    int tid = threadIdx.x;
    int cnt = 0;
#pragma unroll
    for (int i = 0; i < 2; i++) {
        float4 v = row[tid + i * 256];
        cnt += (v.x != 0.f) + (v.y != 0.f) + (v.z != 0.f) + (v.w != 0.f);
    }
    __shared__ int s[8];
#pragma unroll
    for (int o = 16; o > 0; o >>= 1) cnt += __shfl_down_sync(0xffffffffu, cnt, o);
    if ((tid & 31) == 0) s[tid >> 5] = cnt;
    __syncthreads();
    if (tid < 8) {
        int v = s[tid];
#pragma unroll
        for (int o = 4; o > 0; o >>= 1) v += __shfl_down_sync(0xffu, v, o);
        if (tid == 0) g_lengths[b] = v;
    }
}

// ---------------------------------------------------------------------------
// f32x2 helpers
// ---------------------------------------------------------------------------
__device__ __forceinline__ u64 pk2(float lo, float hi) {
    u64 r; asm("mov.b64 %0, {%1,%2};" : "=l"(r) : "f"(lo), "f"(hi)); return r;
}
__device__ __forceinline__ void up2(u64 v, float& lo, float& hi) {
    asm("mov.b64 {%0,%1}, %2;" : "=f"(lo), "=f"(hi) : "l"(v));
}
__device__ __forceinline__ u64 fma2_(u64 a, u64 b, u64 c) {
    u64 d; asm("fma.rn.f32x2 %0, %1, %2, %3;" : "=l"(d) : "l"(a), "l"(b), "l"(c)); return d;
}
__device__ __forceinline__ float fast_tanh(float v) {
    float r; asm("tanh.approx.f32 %0, %1;" : "=f"(r) : "f"(v)); return r;
}

// ---------------------------------------------------------------------------
// LSTM kernel: 1 thread / sequence.
// Pair layout unit-major: P_u = (i_u, f_u), Q_u = (o_u, g_u).
// Sigmoid rows (i,f,o) pre-scaled by 0.5 at load: sig(x) = 0.5*tanh(0.5x)+0.5.
// ---------------------------------------------------------------------------
struct LSTMState {
    u64 h2[HID];   // packed {h_j, h_j}
    float c[HID];
};

__device__ __forceinline__ void lstm_step(
    LSTMState& st, float xv,
    const u64* wihP, const u64* wihQ,
    const u64* bsP,  const u64* bsQ,
    const u64 (*whhP)[HID], const u64 (*whhQ)[HID])
{
    const u64 x2 = pk2(xv, xv);
    u64 aP[HID], aQ[HID];
#pragma unroll
    for (int u = 0; u < HID; u++) {
        u64 a = fma2_(x2, wihP[u], bsP[u]);
        u64 b = fma2_(x2, wihQ[u], bsQ[u]);
#pragma unroll
        for (int j = 0; j < HID; j++) {
            a = fma2_(st.h2[j], whhP[u][j], a);
            b = fma2_(st.h2[j], whhQ[u][j], b);
        }
        aP[u] = a; aQ[u] = b;
    }
#pragma unroll
    for (int u = 0; u < HID; u++) {
        float gi, gf, go, gg;
        up2(aP[u], gi, gf);
        up2(aQ[u], go, gg);
        const float ig = fmaf(fast_tanh(gi), 0.5f, 0.5f);
        const float fg = fmaf(fast_tanh(gf), 0.5f, 0.5f);
        const float og = fmaf(fast_tanh(go), 0.5f, 0.5f);
        const float tg = fast_tanh(gg);
        const float cn = fmaf(fg, st.c[u], ig * tg);
        st.c[u] = cn;
        const float hn = og * fast_tanh(cn);
        st.h2[u] = pk2(hn, hn);
    }
}

__global__ void __launch_bounds__(64, 1) lstm_kernel(
    const float* __restrict__ x,
    const float* __restrict__ W_ih,
    const float* __restrict__ W_hh,
    const float* __restrict__ b_ih,
    const float* __restrict__ b_hh,
    float* __restrict__ out)
{
    int b = blockIdx.x * blockDim.x + threadIdx.x;

    // original gate rows: i:0-4  f:5-9  g:10-14  o:15-19
    // pair P_u = (i_u, f_u) [both *0.5], Q_u = (o_u*0.5, g_u)
    u64 wihP[HID], wihQ[HID], bsP[HID], bsQ[HID];
    u64 whhP[HID][HID], whhQ[HID][HID];
#pragma unroll
    for (int u = 0; u < HID; u++) {
        const int ri = u, rf = HID + u, rg = 2 * HID + u, ro = 3 * HID + u;
        wihP[u] = pk2(0.5f * W_ih[ri], 0.5f * W_ih[rf]);
        wihQ[u] = pk2(0.5f * W_ih[ro], W_ih[rg]);
        bsP[u]  = pk2(0.5f * (b_ih[ri] + b_hh[ri]), 0.5f * (b_ih[rf] + b_hh[rf]));
        bsQ[u]  = pk2(0.5f * (b_ih[ro] + b_hh[ro]), (b_ih[rg] + b_hh[rg]));
#pragma unroll
        for (int j = 0; j < HID; j++) {
            whhP[u][j] = pk2(0.5f * W_hh[ri * HID + j], 0.5f * W_hh[rf * HID + j]);
            whhQ[u][j] = pk2(0.5f * W_hh[ro * HID + j], W_hh[rg * HID + j]);
        }
    }

    const int len = g_lengths[b];
    const float* row = x + (size_t)b * HDIM;

    LSTMState st;
#pragma unroll
    for (int u = 0; u < HID; u++) { st.h2[u] = 0ull; st.c[u] = 0.f; }

    float4 a0 = make_float4(0.f, 0.f, 0.f, 0.f);
    if (len > 0) a0 = *reinterpret_cast<const float4*>(row);

    for (int t0 = 0; t0 < len; t0 += 4) {
        // prefetch next 4 timesteps (HDIM multiple of 4)
        float4 nx = a0;
        const int nt = t0 + 4;
        if (nt < HDIM) nx = *reinterpret_cast<const float4*>(row + nt);

        const int nrem = len - t0;
        if (nrem >= 4) {
            lstm_step(st, a0.x, wihP, wihQ, bsP, bsQ, whhP, whhQ);
            lstm_step(st, a0.y, wihP, wihQ, bsP, bsQ, whhP, whhQ);
            lstm_step(st, a0.z, wihP, wihQ, bsP, bsQ, whhP, whhQ);
            lstm_step(st, a0.w, wihP, wihQ, bsP, bsQ, whhP, whhQ);
        } else {
            float xs[4] = {a0.x, a0.y, a0.z, a0.w};
#pragma unroll
            for (int k = 0; k < 4; k++)
                if (k < nrem)
                    lstm_step(st, xs[k], wihP, wihQ, bsP, bsQ, whhP, whhQ);
        }
        a0 = nx;
    }

#pragma unroll
    for (int u = 0; u < HID; u++) {
        float lo, hi;
        up2(st.h2[u], lo, hi);
        out[b * HID + u] = lo;
    }
}

// ---------------------------------------------------------------------------
extern "C" void kernel_launch(void* const* d_in, const int* in_sizes, int n_in,
                              void* d_out, int out_size) {
    const float* x    = (const float*)d_in[0];
    const float* W_ih = (const float*)d_in[1];
    const float* W_hh = (const float*)d_in[2];
    const float* b_ih = (const float*)d_in[3];
    const float* b_hh = (const float*)d_in[4];
    float* out = (float*)d_out;

    len_kernel<<<BSZ, 256>>>(x);
    lstm_kernel<<<BSZ / 64, 64>>>(x, W_ih, W_hh, b_ih, b_hh, out);
}